// round 1
// baseline (speedup 1.0000x reference)
#include <cuda_runtime.h>

// LowPass filtfilt: order-2 Butterworth, forward+backward IIR, 320 x 200000 fp32.
//
// Key identities used:
//  - scale normalization cancels exactly (linear filter) -> skipped.
//  - IIR poles |z| ~ 0.9726 -> zero-state chunk with WARM=640 warmup samples has
//    state error ~2e-8, far below the 1e-3 threshold. Chunk 0 is exact.
//
// Pass 1: odd-extend x (padlen 9), forward lfilter  -> g_y scratch [320 x 200018]
// Pass 2: lfilter of reversed g_y, reverse+trim     -> out [320 x 200000]

#define NROWS 320
#define NCOLS 200000
#define PAD   9
#define TEXT  (NCOLS + 2 * PAD)          // 200018
#define LCHUNK 1024
#define WARM   640
#define CHUNKS_PER_ROW ((TEXT + LCHUNK - 1) / LCHUNK)   // 196
#define TOTAL_THREADS (NROWS * CHUNKS_PER_ROW)

// Scratch for forward-pass output (alloc-free rule: static __device__ array).
__device__ float g_y[(size_t)NROWS * TEXT];

// Odd-extended input accessor: xe[t], t in [0, TEXT)
__device__ __forceinline__ float get_xe(const float* __restrict__ xr, int t) {
    int i = t - PAD;
    if (i < 0)       return 2.0f * xr[0]         - xr[-i];
    if (i >= NCOLS)  return 2.0f * xr[NCOLS - 1] - xr[2 * NCOLS - 2 - i];
    return xr[i];
}

struct Coef { float b0, b1, b2, a1, a2; };

__device__ __forceinline__ Coef load_coef(const float* __restrict__ bc,
                                          const float* __restrict__ ac) {
    float inv_a0 = 1.0f / ac[0];
    Coef c;
    c.b0 = bc[0] * inv_a0;
    c.b1 = bc[1] * inv_a0;
    c.b2 = bc[2] * inv_a0;
    c.a1 = ac[1] * inv_a0;
    c.a2 = ac[2] * inv_a0;
    return c;
}

// one IIR step: y_t = b0*x_t + b1*x_1 + b2*x_2 - a1*y_1 - a2*y_2
__device__ __forceinline__ float iir_step(const Coef& c, float xt,
                                          float x1, float x2,
                                          float y1, float y2) {
    float fir = fmaf(c.b0, xt, fmaf(c.b1, x1, c.b2 * x2));
    return fir - fmaf(c.a1, y1, c.a2 * y2);
}

__global__ void __launch_bounds__(256)
fwd_kernel(const float* __restrict__ x,
           const float* __restrict__ bc,
           const float* __restrict__ ac) {
    int tid = blockIdx.x * blockDim.x + threadIdx.x;
    if (tid >= TOTAL_THREADS) return;
    int row = tid / CHUNKS_PER_ROW;
    int c   = tid % CHUNKS_PER_ROW;

    const float* xr = x + (size_t)row * NCOLS;
    float* yr = g_y + (size_t)row * TEXT;
    Coef cf = load_coef(bc, ac);

    int t0   = c * LCHUNK;
    int tend = min(TEXT, t0 + LCHUNK);

    float x1 = 0.f, x2 = 0.f, y1 = 0.f, y2 = 0.f;

    if (c > 0) {
        // Warmup region [t0-WARM, t0): always interior of x (start >= 384 > PAD+2),
        // started from zero state; error decays by |pole|^WARM ~ 2e-8.
        const float* xi = xr + (t0 - WARM - PAD);
        x1 = xi[-1];
        x2 = xi[-2];
        #pragma unroll 8
        for (int k = 0; k < WARM; ++k) {
            float xt = xi[k];
            float yt = iir_step(cf, xt, x1, x2, y1, y2);
            x2 = x1; x1 = xt; y2 = y1; y1 = yt;
        }
    }
    // else: chunk 0 starts exactly at t=0 with true zero initial conditions.

    if (t0 >= PAD && tend <= NCOLS + PAD) {
        // Fast path: whole main region maps directly into x.
        const float* xi = xr + (t0 - PAD);
        int len = tend - t0;
        #pragma unroll 8
        for (int k = 0; k < len; ++k) {
            float xt = xi[k];
            float yt = iir_step(cf, xt, x1, x2, y1, y2);
            yr[t0 + k] = yt;
            x2 = x1; x1 = xt; y2 = y1; y1 = yt;
        }
    } else {
        for (int t = t0; t < tend; ++t) {
            float xt = get_xe(xr, t);
            float yt = iir_step(cf, xt, x1, x2, y1, y2);
            yr[t] = yt;
            x2 = x1; x1 = xt; y2 = y1; y1 = yt;
        }
    }
}

__global__ void __launch_bounds__(256)
bwd_kernel(const float* __restrict__ bc,
           const float* __restrict__ ac,
           float* __restrict__ out) {
    int tid = blockIdx.x * blockDim.x + threadIdx.x;
    if (tid >= TOTAL_THREADS) return;
    int row = tid / CHUNKS_PER_ROW;
    int c   = tid % CHUNKS_PER_ROW;

    const float* yr = g_y + (size_t)row * TEXT;
    float* outr = out + (size_t)row * NCOLS;
    Coef cf = load_coef(bc, ac);

    // Reversed view: yrev(s) = yr[TEXT-1-s]
    const float* yrev = yr + (TEXT - 1);

    int s0   = c * LCHUNK;
    int send = min(TEXT, s0 + LCHUNK);

    float p1 = 0.f, p2 = 0.f, z1 = 0.f, z2 = 0.f;

    if (c > 0) {
        int start = s0 - WARM;
        p1 = yrev[-(start - 1)];
        p2 = yrev[-(start - 2)];
        #pragma unroll 8
        for (int k = 0; k < WARM; ++k) {
            int s = start + k;
            float vs = yrev[-s];
            float zs = iir_step(cf, vs, p1, p2, z1, z2);
            p2 = p1; p1 = vs; z2 = z1; z1 = zs;
        }
    }

    #pragma unroll 8
    for (int s = s0; s < send; ++s) {
        float vs = yrev[-s];
        float zs = iir_step(cf, vs, p1, p2, z1, z2);
        p2 = p1; p1 = vs; z2 = z1; z1 = zs;
        // output: result_ext[t] = z[TEXT-1-t], keep t in [PAD, PAD+NCOLS)
        // -> out[NCOLS + PAD - 1 - s] valid for s in [PAD, TEXT - PAD)
        if (s >= PAD && s < TEXT - PAD) {
            outr[NCOLS + PAD - 1 - s] = zs;
        }
    }
}

extern "C" void kernel_launch(void* const* d_in, const int* in_sizes, int n_in,
                              void* d_out, int out_size) {
    const float* x  = (const float*)d_in[0];
    const float* b  = (const float*)d_in[1];
    const float* a  = (const float*)d_in[2];
    float* out = (float*)d_out;

    const int threads = 256;
    const int blocks  = (TOTAL_THREADS + threads - 1) / threads;

    fwd_kernel<<<blocks, threads>>>(x, b, a);
    bwd_kernel<<<blocks, threads>>>(b, a, out);
}

// round 2
// speedup vs baseline: 2.2852x; 2.2852x over previous
#include <cuda_runtime.h>

// LowPass filtfilt: order-2 Butterworth forward+backward IIR, 320 x 200000 fp32.
//
// Round-2 design: warp-cooperative tile staging to make every global access
// coalesced (R1 showed L1=69% / DRAM=10.5% from 32-line-per-LDG strided access).
//
//  - scale normalization cancels (linear filter) -> skipped.
//  - rows split into chunks of L=512; each chunk runs a WARM=384-sample
//    zero-state warmup (state error ~2e-5 << 1e-3 tolerance). Chunk 0 exact.
//  - each warp owns 32 consecutive chunks of one row; per 32-sample tile it
//    cooperatively loads a 32x32 tile (coalesced), filters in smem (in-place,
//    padded rows -> conflict-free), cooperatively stores (coalesced).

#define NROWS 320
#define NCOLS 200000
#define PAD   9
#define TEXT  (NCOLS + 2 * PAD)        // 200018
#define L     512
#define WARM  384
#define TILE  32
#define NT    ((WARM + L) / TILE)      // 28 tiles per chunk (12 warm + 16 main)
#define NT_WARM (WARM / TILE)          // 12
#define CPR   ((TEXT + L - 1) / L)     // 391 chunks per row
#define WPR   ((CPR + 31) / 32)        // 13 warps per row
#define BLOCK_WARPS 8
#define NTHREADS (BLOCK_WARPS * 32)
#define TOTAL_WARPS (NROWS * WPR)      // 4160
#define NBLOCKS (TOTAL_WARPS / BLOCK_WARPS)   // 520 (divides exactly)

// Forward-pass scratch (alloc-free rule: static __device__ array).
__device__ float g_y[(size_t)NROWS * TEXT];

__global__ void __launch_bounds__(NTHREADS)
fwd_kernel(const float* __restrict__ x,
           const float* __restrict__ bc,
           const float* __restrict__ ac) {
    __shared__ float sm[BLOCK_WARPS * 32 * 33];
    const int wid  = threadIdx.x >> 5;
    const int lane = threadIdx.x & 31;
    float* ws = sm + wid * (32 * 33);

    const int gw  = blockIdx.x * BLOCK_WARPS + wid;
    const int row = gw / WPR;
    const int c0  = (gw % WPR) * 32;

    const float* xr = x + (size_t)row * NCOLS;
    float* yr = g_y + (size_t)row * TEXT;

    const float inv = 1.0f / ac[0];
    const float b0 = bc[0] * inv, b1 = bc[1] * inv, b2 = bc[2] * inv;
    const float na1 = -ac[1] * inv, na2 = -ac[2] * inv;

    const int tbase = c0 * L - WARM;   // chunk-row j at tile k: t = tbase + j*L + k

    float x1 = 0.f, x2 = 0.f, y1 = 0.f, y2 = 0.f;

    for (int tile = 0; tile < NT; ++tile) {
        const int koff = tile * TILE;
        // ---- cooperative coalesced load of 32x32 tile (odd-extended input) ----
        #pragma unroll
        for (int j = 0; j < 32; ++j) {
            const int t = tbase + j * L + koff + lane;
            float v = 0.f;
            if (t >= 0 && t < TEXT) {
                const int i = t - PAD;
                if (i < 0)            v = 2.0f * xr[0]         - xr[-i];
                else if (i >= NCOLS)  v = 2.0f * xr[NCOLS - 1] - xr[2 * NCOLS - 2 - i];
                else                  v = xr[i];
            }
            ws[j * 33 + lane] = v;
        }
        __syncwarp();
        // ---- each lane filters its own chunk's 32 samples (in place) ----
        #pragma unroll
        for (int s = 0; s < TILE; ++s) {
            const float xt = ws[lane * 33 + s];
            const float yt = fmaf(na1, y1,
                             fmaf(na2, y2,
                             fmaf(b0, xt, fmaf(b1, x1, b2 * x2))));
            x2 = x1; x1 = xt; y2 = y1; y1 = yt;
            ws[lane * 33 + s] = yt;
        }
        __syncwarp();
        // ---- cooperative coalesced store of main-region tiles ----
        if (tile >= NT_WARM) {
            #pragma unroll
            for (int j = 0; j < 32; ++j) {
                const int t = tbase + j * L + koff + lane;
                if (t < TEXT) yr[t] = ws[j * 33 + lane];
            }
        }
        __syncwarp();
    }
}

__global__ void __launch_bounds__(NTHREADS)
bwd_kernel(const float* __restrict__ bc,
           const float* __restrict__ ac,
           float* __restrict__ out) {
    __shared__ float sm[BLOCK_WARPS * 32 * 33];
    const int wid  = threadIdx.x >> 5;
    const int lane = threadIdx.x & 31;
    float* ws = sm + wid * (32 * 33);

    const int gw  = blockIdx.x * BLOCK_WARPS + wid;
    const int row = gw / WPR;
    const int c0  = (gw % WPR) * 32;

    const float* yr = g_y + (size_t)row * TEXT;
    float* outr = out + (size_t)row * NCOLS;

    const float inv = 1.0f / ac[0];
    const float b0 = bc[0] * inv, b1 = bc[1] * inv, b2 = bc[2] * inv;
    const float na1 = -ac[1] * inv, na2 = -ac[2] * inv;

    const int sbase = c0 * L - WARM;   // reversed-time index s; v(s) = y[TEXT-1-s]

    float p1 = 0.f, p2 = 0.f, z1 = 0.f, z2 = 0.f;

    for (int tile = 0; tile < NT; ++tile) {
        const int koff = tile * TILE;
        // ---- cooperative coalesced load (reversed view of g_y) ----
        #pragma unroll
        for (int j = 0; j < 32; ++j) {
            const int s = sbase + j * L + koff + lane;
            float v = 0.f;
            if (s >= 0 && s < TEXT) v = yr[TEXT - 1 - s];
            ws[j * 33 + lane] = v;
        }
        __syncwarp();
        // ---- filter in place ----
        #pragma unroll
        for (int q = 0; q < TILE; ++q) {
            const float vt = ws[lane * 33 + q];
            const float zt = fmaf(na1, z1,
                             fmaf(na2, z2,
                             fmaf(b0, vt, fmaf(b1, p1, b2 * p2))));
            p2 = p1; p1 = vt; z2 = z1; z1 = zt;
            ws[lane * 33 + q] = zt;
        }
        __syncwarp();
        // ---- cooperative coalesced store (reverse + trim) ----
        if (tile >= NT_WARM) {
            #pragma unroll
            for (int j = 0; j < 32; ++j) {
                const int s = sbase + j * L + koff + lane;
                if (s >= PAD && s < TEXT - PAD)
                    outr[NCOLS + PAD - 1 - s] = ws[j * 33 + lane];
            }
        }
        __syncwarp();
    }
}

extern "C" void kernel_launch(void* const* d_in, const int* in_sizes, int n_in,
                              void* d_out, int out_size) {
    const float* x = (const float*)d_in[0];
    const float* b = (const float*)d_in[1];
    const float* a = (const float*)d_in[2];
    float* out = (float*)d_out;

    fwd_kernel<<<NBLOCKS, NTHREADS>>>(x, b, a);
    bwd_kernel<<<NBLOCKS, NTHREADS>>>(b, a, out);
}